// round 16
// baseline (speedup 1.0000x reference)
#include <cuda_runtime.h>
#include <cuda_fp16.h>
#include <cstdint>
#include <math.h>

// Problem constants
#define S_DIM 500
#define T_DIM 8
#define FO    64
#define CN    4096          // B*T*FO
#define KH    512           // main GEMM K (padded spatial dim), fp16 operands
#define K2    192           // mix GEMM K: [Z|Y1|Y2] fp16

// ---------------- device scratch (allocation-free; zero-initialized) -------
__device__ __half  g_Zh  [S_DIM * CN];          // fp16 activations [s][n]
__device__ __half  g_Ch  [1024 * CN];           // fp16: rows 0..499 As@Z ; 512..1011 As^2@Z
__device__ __half  g_Ahalf[1024 * KH];          // [As; As2] fp16
__device__ __half  g_BT  [KH * KH];             // As^T fp16
__device__ __half  g_Bh  [CN * KH];             // Z^T fp16 [n][k]
__device__ __half  g_Ht  [3 * FO * K2];         // per-layer H^T fp16
__device__ float   g_P   [4 * KH * KH];         // As^2 split-K fp32 partials

// ---------------- helpers ----------------
static __device__ __forceinline__ uint32_t smem_u32(const void* p) {
    uint32_t a;
    asm("{ .reg .u64 t; cvta.to.shared.u64 t, %1; cvt.u32.u64 %0, t; }" : "=r"(a) : "l"(p));
    return a;
}

#define CP_ASYNC16(s, g) asm volatile("cp.async.cg.shared.global [%0], [%1], 16;" :: "r"(s), "l"(g))
#define CP_COMMIT()      asm volatile("cp.async.commit_group;")
#define CP_WAIT0()       asm volatile("cp.async.wait_group 0;")
#define CP_WAIT1()       asm volatile("cp.async.wait_group 1;")

#define LDSM4(r0, r1, r2, r3, a)                                                     \
    asm volatile("ldmatrix.sync.aligned.m8n8.x4.shared.b16 {%0,%1,%2,%3}, [%4];"     \
        : "=r"(r0), "=r"(r1), "=r"(r2), "=r"(r3) : "r"(a))

#define MMA16816(d, a0, a1, a2, a3, b0, b1)                                          \
    asm volatile("mma.sync.aligned.m16n8k16.row.col.f32.f16.f16.f32 "                \
        "{%0,%1,%2,%3}, {%4,%5,%6,%7}, {%8,%9}, {%0,%1,%2,%3};"                      \
        : "+f"((d)[0]), "+f"((d)[1]), "+f"((d)[2]), "+f"((d)[3])                     \
        : "r"(a0), "r"(a1), "r"(a2), "r"(a3), "r"(b0), "r"(b1))

// main GEMM smem row: 64 halves + 8 pad = 144 B
#define SROW 144
#define ATILE_B (128 * SROW)        // 18432  (128 x 64 tile)
#define SM_MAIN (2 * (2 * ATILE_B)) // 73728

// tg_cm smem layout (bytes) — all row strides 16B-aligned for ldmatrix
#define SLAB_B   1040               // 520 halves per slab row (16*65)
#define M0_OFF   0
#define M1_OFF   16640
#define M2_OFF   33280
#define AY_ROW_B 272                // 136 halves (16*17) — ldmatrix-aligned, bank-staggered
#define AY_OFF   49920              // 128 x 272 B = 34816
#define BT2_OFF  84736              // 64 x 400 B = 25600
#define ATF_OFF  110336             // 64 floats
#define B2_OFF   110592             // 64 floats
#define MS_OFF   110848             // 8 floats
#define SM_CM    110880

// ---------------------------------------------------------------------------
// tg_main (R11-proven): C[128x128 tile] = A[m, kz:kz+kLen] @ B[n, ...]^T
// mode 0: half2 store to C.  mode 1: fp32 partial to g_P[z].
// ---------------------------------------------------------------------------
__global__ __launch_bounds__(256)
void tg_main(const __half* __restrict__ A, const __half* __restrict__ B,
             __half* __restrict__ C, int kLen, int ldc, int mode)
{
    extern __shared__ char smem[];
    const uint32_t sb = smem_u32(smem);
    const int BUFSZ = 2 * ATILE_B;

    const int tid  = threadIdx.x;
    const int lane = tid & 31, w = tid >> 5;
    const int wm = w >> 2, wn = w & 3;          // 2 x 4 warps
    const int m0 = blockIdx.y * 128;
    const int n0 = blockIdx.x * 128;
    const int kz = blockIdx.z * kLen;
    const int NIT = kLen >> 6;

    uint32_t aOff[4], bOff[2];
    {
        const int acb = (lane >> 4) * 16;
        #pragma unroll
        for (int i = 0; i < 4; i++) {
            const int r = wm * 64 + i * 16 + ((lane >> 3) & 1) * 8 + (lane & 7);
            aOff[i] = (uint32_t)(r * SROW + acb);
        }
        const int bcb = ((lane >> 3) & 1) * 16;
        #pragma unroll
        for (int p = 0; p < 2; p++) {
            const int r = wn * 32 + p * 16 + (lane >> 4) * 8 + (lane & 7);
            bOff[p] = (uint32_t)(ATILE_B + r * SROW + bcb);
        }
    }

    float acc[4][4][4];
    #pragma unroll
    for (int i = 0; i < 4; i++)
        #pragma unroll
        for (int j = 0; j < 4; j++)
            #pragma unroll
            for (int q = 0; q < 4; q++) acc[i][j][q] = 0.f;

    auto load_tiles = [&](int it, int bufi) {
        const uint32_t dst = sb + bufi * BUFSZ;
        const __half* ga = A + (size_t)m0 * KH + kz + it * 64;
        const __half* gb = B + (size_t)n0 * KH + kz + it * 64;
        #pragma unroll
        for (int i = 0; i < 4; i++) {
            const int ch = i * 256 + tid;
            const int r = ch >> 3, c = ch & 7;
            CP_ASYNC16(dst + r * SROW + c * 16,           ga + (size_t)r * KH + c * 8);
            CP_ASYNC16(dst + ATILE_B + r * SROW + c * 16, gb + (size_t)r * KH + c * 8);
        }
    };

    load_tiles(0, 0);
    CP_COMMIT();

    int buf = 0;
    for (int it = 0; it < NIT; it++) {
        if (it + 1 < NIT) { load_tiles(it + 1, buf ^ 1); CP_COMMIT(); CP_WAIT1(); }
        else             { CP_WAIT0(); }
        __syncthreads();

        const uint32_t base = sb + buf * BUFSZ;
        #pragma unroll
        for (int ks = 0; ks < 4; ks++) {
            uint32_t am[4][4], bm[2][4];
            #pragma unroll
            for (int i = 0; i < 4; i++)
                LDSM4(am[i][0], am[i][1], am[i][2], am[i][3], base + aOff[i] + ks * 32);
            #pragma unroll
            for (int p = 0; p < 2; p++)
                LDSM4(bm[p][0], bm[p][1], bm[p][2], bm[p][3], base + bOff[p] + ks * 32);
            #pragma unroll
            for (int i = 0; i < 4; i++)
                #pragma unroll
                for (int j = 0; j < 4; j++)
                    MMA16816(acc[i][j], am[i][0], am[i][1], am[i][2], am[i][3],
                             bm[j >> 1][(j & 1) * 2], bm[j >> 1][(j & 1) * 2 + 1]);
        }
        __syncthreads();
        buf ^= 1;
    }

    float* Pz = g_P + (size_t)blockIdx.z * (KH * KH);
    #pragma unroll
    for (int i = 0; i < 4; i++) {
        #pragma unroll
        for (int h2 = 0; h2 < 2; h2++) {
            const int row = m0 + wm * 64 + i * 16 + (lane >> 2) + h2 * 8;
            #pragma unroll
            for (int j = 0; j < 4; j++) {
                const int col = n0 + wn * 32 + j * 8 + (lane & 3) * 2;
                const float v0 = acc[i][j][h2 * 2 + 0];
                const float v1 = acc[i][j][h2 * 2 + 1];
                if (mode == 0) {
                    *(__half2*)&C[(size_t)row * ldc + col] = __halves2half2(
                        __float2half_rn(v0), __float2half_rn(v1));
                } else {
                    *(float2*)&Pz[(size_t)row * KH + col] = make_float2(v0, v1);
                }
            }
        }
    }
}

// ---------------------------------------------------------------------------
// k_red: sum 4 fp32 partials -> Ahalf rows 512+ (fp16). grid 128 x 256.
// ---------------------------------------------------------------------------
__global__ __launch_bounds__(256)
void k_red()
{
    const int base = (blockIdx.x * 256 + threadIdx.x) * 8;
    const int P = KH * KH;
    float4 s0 = *(const float4*)&g_P[base];
    float4 s1 = *(const float4*)&g_P[base + 4];
    #pragma unroll
    for (int z = 1; z < 4; z++) {
        const float4 a = *(const float4*)&g_P[z * P + base];
        const float4 b = *(const float4*)&g_P[z * P + base + 4];
        s0.x += a.x; s0.y += a.y; s0.z += a.z; s0.w += a.w;
        s1.x += b.x; s1.y += b.y; s1.z += b.z; s1.w += b.w;
    }
    const int r = base >> 9, c = base & 511;
    __align__(16) __half2 h[4];
    h[0] = __halves2half2(__float2half_rn(s0.x), __float2half_rn(s0.y));
    h[1] = __halves2half2(__float2half_rn(s0.z), __float2half_rn(s0.w));
    h[2] = __halves2half2(__float2half_rn(s1.x), __float2half_rn(s1.y));
    h[3] = __halves2half2(__float2half_rn(s1.z), __float2half_rn(s1.w));
    *(uint4*)&g_Ahalf[(size_t)(512 + r) * KH + c] = *(uint4*)h;
}

// ---------------------------------------------------------------------------
// tg_cm: fused comb + mix (+ final output on last layer).
// CTA = (sc = blockIdx.x [16 s values], b = blockIdx.y).
// ---------------------------------------------------------------------------
__global__ __launch_bounds__(256, 2)
void tg_cm(const __half* __restrict__ Ht, const float* __restrict__ At,
           const float* __restrict__ sv, const float* __restrict__ W2,
           const float* __restrict__ b2, const float* __restrict__ merge,
           float* __restrict__ out, int last)
{
    extern __shared__ char smem[];
    const uint32_t sb = smem_u32(smem);
    const int tid = threadIdx.x;
    const int sc = blockIdx.x;      // s chunk (16 s)
    const int b  = blockIdx.y;

    // ---- phase 1: load slabs + Ht + At (+ b2/merge) ----
    {
        #pragma unroll
        for (int i = 0; i < 4; i++) {
            const int c = i * 256 + tid;        // 0..1023
            const int row = c >> 6, ch = c & 63;
            const int sg = sc * 16 + row;
            const uint32_t dst = sb + row * SLAB_B + ch * 16;
            if (sg < S_DIM) {
                const __half* z  = g_Zh + (size_t)sg * CN + b * 512 + ch * 8;
                const __half* c1 = g_Ch + (size_t)sg * CN + b * 512 + ch * 8;
                const __half* c2 = g_Ch + (size_t)(512 + sg) * CN + b * 512 + ch * 8;
                CP_ASYNC16(dst + M0_OFF, z);
                CP_ASYNC16(dst + M1_OFF, c1);
                CP_ASYNC16(dst + M2_OFF, c2);
            } else {
                const uint4 zz = make_uint4(0, 0, 0, 0);
                *(uint4*)(smem + M0_OFF + row * SLAB_B + ch * 16) = zz;
                *(uint4*)(smem + M1_OFF + row * SLAB_B + ch * 16) = zz;
                *(uint4*)(smem + M2_OFF + row * SLAB_B + ch * 16) = zz;
            }
        }
        #pragma unroll
        for (int i = 0; i < 6; i++) {
            const int c = i * 256 + tid;        // 0..1535
            const int g = c / 24, ch = c - g * 24;
            CP_ASYNC16(sb + BT2_OFF + g * 400 + ch * 16, Ht + g * K2 + ch * 8);
        }
        if (tid < 64) {
            ((float*)(smem + ATF_OFF))[tid] = At[tid];
            ((float*)(smem + B2_OFF))[tid]  = b2[tid];
        }
        if (tid < 8) ((float*)(smem + MS_OFF))[tid] = merge[tid];
        CP_COMMIT();
        CP_WAIT0();
        __syncthreads();
    }

    // ---- phase 2: comb (temporal mixing) into aY smem ----
    {
        const float* sAt = (const float*)(smem + ATF_OFF);
        const float s0 = sv[0], s1 = sv[1], s2 = sv[2], s3 = sv[3];
        const float c00 = s0 * s0, c01 = 2.f * s0 * s1, c02 = s1 * s1;
        const float c10 = 2.f * s0 * s2, c11 = 2.f * (s0 * s3 + s1 * s2), c12 = 2.f * s1 * s3;
        const float c20 = s2 * s2, c21 = 2.f * s2 * s3, c22 = s3 * s3;

        const int f = tid & 63, sq = tid >> 6;
        const __half* p0 = (const __half*)(smem + M0_OFF);
        const __half* p1 = (const __half*)(smem + M1_OFF);
        const __half* p2 = (const __half*)(smem + M2_OFF);

        #pragma unroll
        for (int q = 0; q < 4; q++) {
            const int sl = sq + q * 4;
            float m0[8], m1v[8], m2v[8];
            #pragma unroll
            for (int t = 0; t < 8; t++) {
                m0[t]  = __half2float(p0[sl * 520 + t * 64 + f]);
                m1v[t] = __half2float(p1[sl * 520 + t * 64 + f]);
                m2v[t] = __half2float(p2[sl * 520 + t * 64 + f]);
            }
            float n10[8], n11[8], n12[8];
            #pragma unroll
            for (int t = 0; t < 8; t++) {
                float a0 = 0.f, a1 = 0.f, a2 = 0.f;
                #pragma unroll
                for (int u = 0; u < 8; u++) {
                    const float wv = sAt[t * 8 + u];
                    a0 += wv * m0[u]; a1 += wv * m1v[u]; a2 += wv * m2v[u];
                }
                n10[t] = a0; n11[t] = a1; n12[t] = a2;
            }
            #pragma unroll
            for (int t = 0; t < 8; t++) {
                float a0 = 0.f, a1 = 0.f, a2 = 0.f;
                #pragma unroll
                for (int u = 0; u < 8; u++) {
                    const float wv = sAt[t * 8 + u];
                    a0 += wv * n10[u]; a1 += wv * n11[u]; a2 += wv * n12[u];
                }
                const float y1 = s0 * m0[t] + s1 * m1v[t] + s2 * n10[t] + s3 * n11[t];
                const float y2 = c00 * m0[t] + c01 * m1v[t] + c02 * m2v[t]
                               + c10 * n10[t] + c11 * n11[t] + c12 * n12[t]
                               + c20 * a0 + c21 * a1 + c22 * a2;
                const int row = t * 16 + sl;
                __half* ayr = (__half*)(smem + AY_OFF + row * AY_ROW_B);
                ayr[f]      = __float2half_rn(y1);
                ayr[64 + f] = __float2half_rn(y2);
            }
        }
    }
    __syncthreads();

    // ---- phase 3: GEMM M=128 N=64 K=192 (kb0 from m0 slab; kb1/2 from aY) ----
    const int lane = tid & 31, w = tid >> 5;
    const int wm = w >> 1, wn = w & 1;      // 4(M) x 2(N) warps
    float acc[2][4][4];
    #pragma unroll
    for (int i = 0; i < 2; i++)
        #pragma unroll
        for (int j = 0; j < 4; j++)
            #pragma unroll
            for (int q = 0; q < 4; q++) acc[i][j][q] = 0.f;
    {
        uint32_t aM0[2], aYo[2], bO[2];
        #pragma unroll
        for (int i = 0; i < 2; i++) {
            const int r = wm * 32 + i * 16 + ((lane >> 3) & 1) * 8 + (lane & 7);
            aM0[i] = sb + M0_OFF + (r & 15) * SLAB_B + (r >> 4) * 128 + (lane >> 4) * 16;
            aYo[i] = sb + AY_OFF + r * AY_ROW_B + (lane >> 4) * 16;
        }
        #pragma unroll
        for (int p = 0; p < 2; p++) {
            const int rB = wn * 32 + p * 16 + (lane >> 4) * 8 + (lane & 7);
            bO[p] = sb + BT2_OFF + rB * 400 + ((lane >> 3) & 1) * 16;
        }
        #pragma unroll
        for (int kb = 0; kb < 3; kb++) {
            #pragma unroll
            for (int ks = 0; ks < 4; ks++) {
                uint32_t am[2][4], bm[2][4];
                #pragma unroll
                for (int i = 0; i < 2; i++) {
                    const uint32_t a = (kb == 0) ? (aM0[i] + ks * 32)
                                                 : (aYo[i] + (kb - 1) * 128 + ks * 32);
                    LDSM4(am[i][0], am[i][1], am[i][2], am[i][3], a);
                }
                #pragma unroll
                for (int p = 0; p < 2; p++)
                    LDSM4(bm[p][0], bm[p][1], bm[p][2], bm[p][3],
                          bO[p] + kb * 128 + ks * 32);
                #pragma unroll
                for (int i = 0; i < 2; i++)
                    #pragma unroll
                    for (int j = 0; j < 4; j++)
                        MMA16816(acc[i][j], am[i][0], am[i][1], am[i][2], am[i][3],
                                 bm[j >> 1][(j & 1) * 2], bm[j >> 1][(j & 1) * 2 + 1]);
            }
        }
    }

    // ---- phase 4: epilogue ----
    __syncthreads();
    __half* zs = (__half*)(smem + AY_OFF);   // reuse: [128 r][72] halves (144B rows)
    #pragma unroll
    for (int i = 0; i < 2; i++) {
        #pragma unroll
        for (int h2 = 0; h2 < 2; h2++) {
            const int r = wm * 32 + i * 16 + (lane >> 2) + h2 * 8;
            const int t = r >> 4, sl = r & 15;
            const int sg = sc * 16 + sl;
            #pragma unroll
            for (int j = 0; j < 4; j++) {
                const int col = wn * 32 + j * 8 + (lane & 3) * 2;
                const __half h0 = __float2half_rn(tanhf(acc[i][j][h2 * 2 + 0]));
                const __half h1 = __float2half_rn(tanhf(acc[i][j][h2 * 2 + 1]));
                *(__half2*)&zs[r * 72 + col] = __halves2half2(h0, h1);
                if (sg < S_DIM)
                    *(__half2*)&g_Zh[(size_t)sg * CN + (b * 8 + t) * 64 + col] =
                        __halves2half2(h0, h1);
            }
        }
    }
    __syncthreads();

    if (!last) {
        // emit next layer's B operand: Bh[(b*8+t)*64+f][sc*16 .. +15]
        #pragma unroll
        for (int it = 0; it < 2; it++) {
            const int rho = it * 256 + tid;     // 0..511
            const int t = rho >> 6, f = rho & 63;
            __align__(16) __half v[16];
            #pragma unroll
            for (int k = 0; k < 16; k++)
                v[k] = zs[(t * 16 + k) * 72 + f];
            __half* dst = g_Bh + (size_t)((b * 8 + t) * 64 + f) * KH + sc * 16;
            *(uint4*)dst       = *(uint4*)v;
            *(uint4*)(dst + 8) = *(uint4*)(v + 8);
        }
    } else {
        // final output: out[b, s, g] = W2 @ (sum_t merge[t] z[t,s,:]) + msum*b2
        float* w2s = (float*)(smem + M1_OFF);   // [64 g][65] floats
        float* us  = (float*)(smem + M2_OFF);   // [16 sl][65] floats
        const float* ms = (const float*)(smem + MS_OFF);
        for (int idx = tid; idx < 4096; idx += 256)
            w2s[(idx >> 6) * 65 + (idx & 63)] = W2[idx];
        const float msum = ms[0] + ms[1] + ms[2] + ms[3] + ms[4] + ms[5] + ms[6] + ms[7];
        const int f = tid & 63, sq = tid >> 6;
        #pragma unroll
        for (int q = 0; q < 4; q++) {
            const int sl = sq + q * 4;
            float u = 0.f;
            #pragma unroll
            for (int t = 0; t < 8; t++)
                u += ms[t] * __half2float(zs[(t * 16 + sl) * 72 + f]);
            us[sl * 65 + f] = u;
        }
        __syncthreads();
        const float* b2s = (const float*)(smem + B2_OFF);
        #pragma unroll
        for (int q = 0; q < 4; q++) {
            const int sl = sq + q * 4;
            const int sg = sc * 16 + sl;
            if (sg < S_DIM) {
                float o = msum * b2s[f];
                #pragma unroll 8
                for (int k = 0; k < 64; k++)
                    o += w2s[f * 65 + k] * us[sl * 65 + k];
                out[(size_t)(b * S_DIM + sg) * 64 + f] = o;
            }
        }
    }
}

// ---------------------------------------------------------------------------
// k_prep: merged inproj + As conversion + Ht conversion.  grid (64, 15).
// ---------------------------------------------------------------------------
__global__ __launch_bounds__(256)
void k_prep(const float* __restrict__ x, const float* __restrict__ W1,
            const float* __restrict__ b1, const float* __restrict__ As,
            const float* __restrict__ H)
{
    __shared__ float xs[52][32];
    __shared__ __half hs[64][52];
    __shared__ float tile[32][33];

    const int tid = threadIdx.x;

    if (blockIdx.y < 10) {
        const int bt  = blockIdx.x;
        const int s0  = blockIdx.y * 50;
        const int f   = tid & 63;
        const int sl0 = tid >> 6;

        float wreg[32];
        #pragma unroll
        for (int i = 0; i < 32; i++) wreg[i] = __ldg(&W1[f * 32 + i]);
        const float bias = __ldg(&b1[f]);

        const float* xp = x + (bt * S_DIM + s0) * 32;
        for (int idx = tid; idx < 50 * 32; idx += 256)
            xs[idx >> 5][idx & 31] = xp[idx];
        if (tid < 64) xs[50 + (tid >> 5)][tid & 31] = 0.f;
        __syncthreads();

        float acc[13];
        #pragma unroll
        for (int q = 0; q < 13; q++) acc[q] = bias;
        #pragma unroll
        for (int i = 0; i < 32; i++) {
            const float wv = wreg[i];
            #pragma unroll
            for (int q = 0; q < 13; q++)
                acc[q] += xs[q * 4 + sl0][i] * wv;
        }
        #pragma unroll
        for (int q = 0; q < 13; q++) {
            const int sl = q * 4 + sl0;
            if (sl < 50) {
                const __half h = __float2half_rn(acc[q]);
                g_Zh[(size_t)(s0 + sl) * CN + bt * 64 + f] = h;
                hs[f][sl] = h;
            }
        }
        __syncthreads();

        for (int idx = tid; idx < 64 * 50; idx += 256) {
            const int r = idx / 50, c = idx - r * 50;
            g_Bh[(size_t)(bt * 64 + r) * KH + s0 + c] = hs[r][c];
        }
        return;
    }

    const int idx = (blockIdx.y - 10) * 64 + blockIdx.x;
    if (idx < 256) {
        const int tr = tid >> 5, tc = tid & 31;
        const int r0 = (idx >> 4) * 32, c0 = (idx & 15) * 32;

        #pragma unroll
        for (int ii = 0; ii < 4; ii++) {
            const int r = r0 + tr + ii * 8, c = c0 + tc;
            float v = (r < S_DIM && c < S_DIM) ? As[r * S_DIM + c] : 0.f;
            g_Ahalf[(size_t)r * KH + c] = __float2half_rn(v);
            tile[tr + ii * 8][tc] = v;
        }
        __syncthreads();
        #pragma unroll
        for (int ii = 0; ii < 4; ii++) {
            const int a = tr + ii * 8;
            g_BT[(size_t)(c0 + a) * KH + r0 + tc] = __float2half_rn(tile[tc][a]);
        }
    } else if (idx < 259) {
        const int l = idx - 256;
        for (int i = tid; i < 3 * 64 * 64; i += 256) {
            const int seg = i >> 12, rem = i & 4095;
            const int f = rem >> 6, g = rem & 63;
            g_Ht[(size_t)l * FO * K2 + (size_t)g * K2 + seg * 64 + f] =
                __float2half_rn(H[l * 12288 + seg * 4096 + f * 64 + g]);
        }
    }
}

// ---------------------------------------------------------------------------
extern "C" void kernel_launch(void* const* d_in, const int* in_sizes, int n_in,
                              void* d_out, int out_size)
{
    const float* x     = (const float*)d_in[0];
    const float* At    = (const float*)d_in[1];
    const float* As    = (const float*)d_in[2];
    const float* sv    = (const float*)d_in[3];
    const float* H     = (const float*)d_in[4];
    const float* W1    = (const float*)d_in[5];
    const float* b1    = (const float*)d_in[6];
    const float* W2    = (const float*)d_in[7];
    const float* b2    = (const float*)d_in[8];
    const float* merge = (const float*)d_in[9];
    float* out = (float*)d_out;

    cudaFuncSetAttribute(tg_main, cudaFuncAttributeMaxDynamicSharedMemorySize, SM_MAIN);
    cudaFuncSetAttribute(tg_cm,   cudaFuncAttributeMaxDynamicSharedMemorySize, SM_CM);

    __half *Ah, *BT, *Bh, *Ht, *Ch;
    cudaGetSymbolAddress((void**)&Ah, g_Ahalf);
    cudaGetSymbolAddress((void**)&BT, g_BT);
    cudaGetSymbolAddress((void**)&Bh, g_Bh);
    cudaGetSymbolAddress((void**)&Ht, g_Ht);
    cudaGetSymbolAddress((void**)&Ch, g_Ch);

    // 0: inproj + As conversion + Ht conversion (merged)
    k_prep<<<dim3(64, 15), 256>>>(x, W1, b1, As, H);
    // 1: As2 = As @ As via split-K x4 (fp32 partials)
    tg_main<<<dim3(4, 4, 4), 256, SM_MAIN>>>(Ah, BT, Ch, 128, KH, 1);
    // 2: reduce partials -> Ahalf rows 512+
    k_red<<<128, 256>>>();

    for (int l = 0; l < 3; l++) {
        // main GEMM Ch[1024,4096] = [As;As2] @ Z^T, K=512
        tg_main<<<dim3(32, 8, 1), 256, SM_MAIN>>>(Ah, Bh, Ch, KH, CN, 0);
        // fused comb + mix (+ final out on last layer)
        tg_cm<<<dim3(32, 8), 256, SM_CM>>>(Ht + (size_t)l * FO * K2, At, sv,
                                           W2, b2, merge, out, l == 2 ? 1 : 0);
    }
}

// round 17
// speedup vs baseline: 1.4818x; 1.4818x over previous
#include <cuda_runtime.h>
#include <cuda_fp16.h>
#include <cstdint>
#include <math.h>

// Problem constants
#define S_DIM 500
#define T_DIM 8
#define FO    64
#define CN    4096          // B*T*FO
#define KH    512           // main GEMM K (padded spatial dim), fp16 operands
#define K2    192           // mix GEMM K: [Z|Y1|Y2] fp16
#define M2P   32768         // mix rows: 64 bt * 512 (s padded)

// ---------------- device scratch (allocation-free; zero-initialized) -------
__device__ __half  g_Zh  [S_DIM * CN];          // fp16 activations [s][n]
__device__ __half  g_Ch  [1024 * CN];           // fp16: rows 0..499 As@Z ; 512..1011 As^2@Z
__device__ __half  g_Ahalf[1024 * KH];          // [As; As2] fp16
__device__ __half  g_BT  [KH * KH];             // As^T fp16
__device__ __half  g_Bh  [CN * KH];             // Z^T fp16 [n][k]
__device__ __half  g_A2  [(size_t)M2P * K2];    // mix A operand, row = bt*512 + s
__device__ __half  g_Ht  [3 * FO * K2];         // per-layer H^T fp16
__device__ float   g_P   [4 * KH * KH];         // As^2 split-K fp32 partials

// ---------------- helpers ----------------
static __device__ __forceinline__ uint32_t smem_u32(const void* p) {
    uint32_t a;
    asm("{ .reg .u64 t; cvta.to.shared.u64 t, %1; cvt.u32.u64 %0, t; }" : "=r"(a) : "l"(p));
    return a;
}

#define CP_ASYNC16(s, g) asm volatile("cp.async.cg.shared.global [%0], [%1], 16;" :: "r"(s), "l"(g))
#define CP_COMMIT()      asm volatile("cp.async.commit_group;")
#define CP_WAIT0()       asm volatile("cp.async.wait_group 0;")
#define CP_WAIT1()       asm volatile("cp.async.wait_group 1;")

#define LDSM4(r0, r1, r2, r3, a)                                                     \
    asm volatile("ldmatrix.sync.aligned.m8n8.x4.shared.b16 {%0,%1,%2,%3}, [%4];"     \
        : "=r"(r0), "=r"(r1), "=r"(r2), "=r"(r3) : "r"(a))

#define MMA16816(d, a0, a1, a2, a3, b0, b1)                                          \
    asm volatile("mma.sync.aligned.m16n8k16.row.col.f32.f16.f16.f32 "                \
        "{%0,%1,%2,%3}, {%4,%5,%6,%7}, {%8,%9}, {%0,%1,%2,%3};"                      \
        : "+f"((d)[0]), "+f"((d)[1]), "+f"((d)[2]), "+f"((d)[3])                     \
        : "r"(a0), "r"(a1), "r"(a2), "r"(a3), "r"(b0), "r"(b1))

// smem row: 64 halves + 8 pad = 144 B (ldmatrix conflict-free)
#define SROW 144
#define ATILE_B (128 * SROW)        // 18432  (128 x 64 tile)
#define BTILE2_B (64 * SROW)        // 9216   (64 x 64 tile)
#define SM_MAIN (2 * (2 * ATILE_B))          // 73728
#define SM_MIX  (2 * (ATILE_B + BTILE2_B))   // 55296

// ---------------------------------------------------------------------------
// tg_main (R11-proven): C[128x128 tile] = A[m, kz:kz+kLen] @ B[n, ...]^T
// mode 0: half2 store to C.  mode 1: fp32 partial to g_P[z].
// BM=128 BN=128 BK=64, 256 thr, warps 2(M)x4(N), warp tile 64x32, 2-stage.
// ---------------------------------------------------------------------------
__global__ __launch_bounds__(256)
void tg_main(const __half* __restrict__ A, const __half* __restrict__ B,
             __half* __restrict__ C, int kLen, int ldc, int mode)
{
    extern __shared__ char smem[];
    const uint32_t sb = smem_u32(smem);
    const int BUFSZ = 2 * ATILE_B;

    const int tid  = threadIdx.x;
    const int lane = tid & 31, w = tid >> 5;
    const int wm = w >> 2, wn = w & 3;          // 2 x 4 warps
    const int m0 = blockIdx.y * 128;
    const int n0 = blockIdx.x * 128;
    const int kz = blockIdx.z * kLen;
    const int NIT = kLen >> 6;

    uint32_t aOff[4], bOff[2];
    {
        const int acb = (lane >> 4) * 16;
        #pragma unroll
        for (int i = 0; i < 4; i++) {
            const int r = wm * 64 + i * 16 + ((lane >> 3) & 1) * 8 + (lane & 7);
            aOff[i] = (uint32_t)(r * SROW + acb);
        }
        const int bcb = ((lane >> 3) & 1) * 16;
        #pragma unroll
        for (int p = 0; p < 2; p++) {
            const int r = wn * 32 + p * 16 + (lane >> 4) * 8 + (lane & 7);
            bOff[p] = (uint32_t)(ATILE_B + r * SROW + bcb);
        }
    }

    float acc[4][4][4];
    #pragma unroll
    for (int i = 0; i < 4; i++)
        #pragma unroll
        for (int j = 0; j < 4; j++)
            #pragma unroll
            for (int q = 0; q < 4; q++) acc[i][j][q] = 0.f;

    auto load_tiles = [&](int it, int bufi) {
        const uint32_t dst = sb + bufi * BUFSZ;
        const __half* ga = A + (size_t)m0 * KH + kz + it * 64;
        const __half* gb = B + (size_t)n0 * KH + kz + it * 64;
        #pragma unroll
        for (int i = 0; i < 4; i++) {
            const int ch = i * 256 + tid;       // 0..1023
            const int r = ch >> 3, c = ch & 7;
            CP_ASYNC16(dst + r * SROW + c * 16,           ga + (size_t)r * KH + c * 8);
            CP_ASYNC16(dst + ATILE_B + r * SROW + c * 16, gb + (size_t)r * KH + c * 8);
        }
    };

    load_tiles(0, 0);
    CP_COMMIT();

    int buf = 0;
    for (int it = 0; it < NIT; it++) {
        if (it + 1 < NIT) { load_tiles(it + 1, buf ^ 1); CP_COMMIT(); CP_WAIT1(); }
        else             { CP_WAIT0(); }
        __syncthreads();

        const uint32_t base = sb + buf * BUFSZ;
        #pragma unroll
        for (int ks = 0; ks < 4; ks++) {
            uint32_t am[4][4], bm[2][4];
            #pragma unroll
            for (int i = 0; i < 4; i++)
                LDSM4(am[i][0], am[i][1], am[i][2], am[i][3], base + aOff[i] + ks * 32);
            #pragma unroll
            for (int p = 0; p < 2; p++)
                LDSM4(bm[p][0], bm[p][1], bm[p][2], bm[p][3], base + bOff[p] + ks * 32);
            #pragma unroll
            for (int i = 0; i < 4; i++)
                #pragma unroll
                for (int j = 0; j < 4; j++)
                    MMA16816(acc[i][j], am[i][0], am[i][1], am[i][2], am[i][3],
                             bm[j >> 1][(j & 1) * 2], bm[j >> 1][(j & 1) * 2 + 1]);
        }
        __syncthreads();
        buf ^= 1;
    }

    float* Pz = g_P + (size_t)blockIdx.z * (KH * KH);
    #pragma unroll
    for (int i = 0; i < 4; i++) {
        #pragma unroll
        for (int h2 = 0; h2 < 2; h2++) {
            const int row = m0 + wm * 64 + i * 16 + (lane >> 2) + h2 * 8;
            #pragma unroll
            for (int j = 0; j < 4; j++) {
                const int col = n0 + wn * 32 + j * 8 + (lane & 3) * 2;
                const float v0 = acc[i][j][h2 * 2 + 0];
                const float v1 = acc[i][j][h2 * 2 + 1];
                if (mode == 0) {
                    *(__half2*)&C[(size_t)row * ldc + col] = __halves2half2(
                        __float2half_rn(v0), __float2half_rn(v1));
                } else {
                    *(float2*)&Pz[(size_t)row * KH + col] = make_float2(v0, v1);
                }
            }
        }
    }
}

// ---------------------------------------------------------------------------
// k_red: sum 4 fp32 partials -> Ahalf rows 512+ (fp16). grid 128 x 256,
// 8 floats/thread via float4 (high ILP).
// ---------------------------------------------------------------------------
__global__ __launch_bounds__(256)
void k_red()
{
    const int base = (blockIdx.x * 256 + threadIdx.x) * 8;  // < 262144
    const int P = KH * KH;
    float4 s0 = *(const float4*)&g_P[base];
    float4 s1 = *(const float4*)&g_P[base + 4];
    #pragma unroll
    for (int z = 1; z < 4; z++) {
        const float4 a = *(const float4*)&g_P[z * P + base];
        const float4 b = *(const float4*)&g_P[z * P + base + 4];
        s0.x += a.x; s0.y += a.y; s0.z += a.z; s0.w += a.w;
        s1.x += b.x; s1.y += b.y; s1.z += b.z; s1.w += b.w;
    }
    const int r = base >> 9, c = base & 511;
    __align__(16) __half2 h[4];
    h[0] = __halves2half2(__float2half_rn(s0.x), __float2half_rn(s0.y));
    h[1] = __halves2half2(__float2half_rn(s0.z), __float2half_rn(s0.w));
    h[2] = __halves2half2(__float2half_rn(s1.x), __float2half_rn(s1.y));
    h[3] = __halves2half2(__float2half_rn(s1.z), __float2half_rn(s1.w));
    *(uint4*)&g_Ahalf[(size_t)(512 + r) * KH + c] = *(uint4*)h;
}

// ---------------------------------------------------------------------------
// tg_mix: rows m = bt*512 + s.  out = tanh(A2 @ Ht^T).  (R11/R14 proven)
// writeB=0 skips the g_Bh emission (last layer).
// ---------------------------------------------------------------------------
__global__ __launch_bounds__(256)
void tg_mix(const __half* __restrict__ A, const __half* __restrict__ B, int writeB)
{
    extern __shared__ char smem[];
    const uint32_t sb = smem_u32(smem);
    const int BUFSZ = ATILE_B + BTILE2_B;

    const int tid  = threadIdx.x;
    const int lane = tid & 31, w = tid >> 5;
    const int wm = w >> 1, wn = w & 1;      // 4 x 2 warps
    const int r0 = blockIdx.x * 128;
    const int bt = r0 >> 9;
    const int s_base = r0 & 511;
    const int K = K2;
    const int NIT = K / 64;                 // 3

    uint32_t aOff[2], bOff[2];
    {
        const int acb = (lane >> 4) * 16;
        #pragma unroll
        for (int i = 0; i < 2; i++) {
            const int r = wm * 32 + i * 16 + ((lane >> 3) & 1) * 8 + (lane & 7);
            aOff[i] = (uint32_t)(r * SROW + acb);
        }
        const int bcb = ((lane >> 3) & 1) * 16;
        #pragma unroll
        for (int p = 0; p < 2; p++) {
            const int r = wn * 32 + p * 16 + (lane >> 4) * 8 + (lane & 7);
            bOff[p] = (uint32_t)(ATILE_B + r * SROW + bcb);
        }
    }

    float acc[2][4][4];
    #pragma unroll
    for (int i = 0; i < 2; i++)
        #pragma unroll
        for (int j = 0; j < 4; j++)
            #pragma unroll
            for (int q = 0; q < 4; q++) acc[i][j][q] = 0.f;

    auto load_tiles = [&](int it, int bufi) {
        const uint32_t dst = sb + bufi * BUFSZ;
        const __half* ga = A + (size_t)r0 * K + it * 64;
        const __half* gb = B + it * 64;
        #pragma unroll
        for (int i = 0; i < 4; i++) {
            const int ch = i * 256 + tid;
            const int r = ch >> 3, c = ch & 7;
            CP_ASYNC16(dst + r * SROW + c * 16, ga + (size_t)r * K + c * 8);
        }
        #pragma unroll
        for (int i = 0; i < 2; i++) {
            const int ch = i * 256 + tid;
            const int r = ch >> 3, c = ch & 7;
            CP_ASYNC16(dst + ATILE_B + r * SROW + c * 16, gb + (size_t)r * K + c * 8);
        }
    };

    load_tiles(0, 0);
    CP_COMMIT();

    int buf = 0;
    for (int it = 0; it < NIT; it++) {
        if (it + 1 < NIT) { load_tiles(it + 1, buf ^ 1); CP_COMMIT(); CP_WAIT1(); }
        else             { CP_WAIT0(); }
        __syncthreads();

        const uint32_t base = sb + buf * BUFSZ;
        #pragma unroll
        for (int ks = 0; ks < 4; ks++) {
            uint32_t am[2][4], bm[2][4];
            #pragma unroll
            for (int i = 0; i < 2; i++)
                LDSM4(am[i][0], am[i][1], am[i][2], am[i][3], base + aOff[i] + ks * 32);
            #pragma unroll
            for (int p = 0; p < 2; p++)
                LDSM4(bm[p][0], bm[p][1], bm[p][2], bm[p][3], base + bOff[p] + ks * 32);
            #pragma unroll
            for (int i = 0; i < 2; i++)
                #pragma unroll
                for (int j = 0; j < 4; j++)
                    MMA16816(acc[i][j], am[i][0], am[i][1], am[i][2], am[i][3],
                             bm[j >> 1][(j & 1) * 2], bm[j >> 1][(j & 1) * 2 + 1]);
        }
        __syncthreads();
        buf ^= 1;
    }

    // epilogue: tanh -> g_Zh (fp16) + smem transpose -> g_Bh (unless last layer)
    __syncthreads();
    __half* hsm = (__half*)smem;             // [64 f][136 s] halves
    #pragma unroll
    for (int i = 0; i < 2; i++) {
        #pragma unroll
        for (int h2 = 0; h2 < 2; h2++) {
            const int sl = wm * 32 + i * 16 + (lane >> 2) + h2 * 8;   // local s
            const int s  = s_base + sl;
            #pragma unroll
            for (int j = 0; j < 4; j++) {
                const int f0 = wn * 32 + j * 8 + (lane & 3) * 2;
                const __half h0 = __float2half_rn(tanhf(acc[i][j][h2 * 2 + 0]));
                const __half h1 = __float2half_rn(tanhf(acc[i][j][h2 * 2 + 1]));
                hsm[f0 * 136 + sl]       = h0;
                hsm[(f0 + 1) * 136 + sl] = h1;
                if (s < S_DIM)
                    *(__half2*)&g_Zh[(size_t)s * CN + bt * 64 + f0] = __halves2half2(h0, h1);
            }
        }
    }
    if (writeB) {
        __syncthreads();
        for (int idx = tid; idx < 512; idx += 256) {
            const int f = idx >> 3, ch = idx & 7;
            const int so = ch * 16;
            const uint4 v0 = *(const uint4*)&hsm[f * 136 + so];
            const uint4 v1 = *(const uint4*)&hsm[f * 136 + so + 8];
            __half* dst = g_Bh + (size_t)(bt * 64 + f) * KH + s_base + so;
            *(uint4*)dst       = v0;
            *(uint4*)(dst + 8) = v1;
        }
    }
}

// ---------------------------------------------------------------------------
// k_prep: merged inproj + As conversion + Ht conversion.  grid (64, 15).
// ---------------------------------------------------------------------------
__global__ __launch_bounds__(256)
void k_prep(const float* __restrict__ x, const float* __restrict__ W1,
            const float* __restrict__ b1, const float* __restrict__ As,
            const float* __restrict__ H)
{
    __shared__ float xs[52][32];
    __shared__ __half hs[64][52];
    __shared__ float tile[32][33];

    const int tid = threadIdx.x;

    if (blockIdx.y < 10) {
        const int bt  = blockIdx.x;
        const int s0  = blockIdx.y * 50;
        const int f   = tid & 63;
        const int sl0 = tid >> 6;

        float wreg[32];
        #pragma unroll
        for (int i = 0; i < 32; i++) wreg[i] = __ldg(&W1[f * 32 + i]);
        const float bias = __ldg(&b1[f]);

        const float* xp = x + (bt * S_DIM + s0) * 32;
        for (int idx = tid; idx < 50 * 32; idx += 256)
            xs[idx >> 5][idx & 31] = xp[idx];
        if (tid < 64) xs[50 + (tid >> 5)][tid & 31] = 0.f;
        __syncthreads();

        float acc[13];
        #pragma unroll
        for (int q = 0; q < 13; q++) acc[q] = bias;
        #pragma unroll
        for (int i = 0; i < 32; i++) {
            const float wv = wreg[i];
            #pragma unroll
            for (int q = 0; q < 13; q++)
                acc[q] += xs[q * 4 + sl0][i] * wv;
        }
        #pragma unroll
        for (int q = 0; q < 13; q++) {
            const int sl = q * 4 + sl0;
            if (sl < 50) {
                const __half h = __float2half_rn(acc[q]);
                g_Zh[(size_t)(s0 + sl) * CN + bt * 64 + f] = h;
                hs[f][sl] = h;
            }
        }
        __syncthreads();

        for (int idx = tid; idx < 64 * 50; idx += 256) {
            const int r = idx / 50, c = idx - r * 50;
            g_Bh[(size_t)(bt * 64 + r) * KH + s0 + c] = hs[r][c];
        }
        return;
    }

    const int idx = (blockIdx.y - 10) * 64 + blockIdx.x;
    if (idx < 256) {
        const int tr = tid >> 5, tc = tid & 31;
        const int r0 = (idx >> 4) * 32, c0 = (idx & 15) * 32;

        #pragma unroll
        for (int ii = 0; ii < 4; ii++) {
            const int r = r0 + tr + ii * 8, c = c0 + tc;
            float v = (r < S_DIM && c < S_DIM) ? As[r * S_DIM + c] : 0.f;
            g_Ahalf[(size_t)r * KH + c] = __float2half_rn(v);
            tile[tr + ii * 8][tc] = v;
        }
        __syncthreads();
        #pragma unroll
        for (int ii = 0; ii < 4; ii++) {
            const int a = tr + ii * 8;
            g_BT[(size_t)(c0 + a) * KH + r0 + tc] = __float2half_rn(tile[tc][a]);
        }
    } else if (idx < 259) {
        const int l = idx - 256;
        for (int i = tid; i < 3 * 64 * 64; i += 256) {
            const int seg = i >> 12, rem = i & 4095;
            const int f = rem >> 6, g = rem & 63;
            g_Ht[(size_t)l * FO * K2 + (size_t)g * K2 + seg * 64 + f] =
                __float2half_rn(H[l * 12288 + seg * 4096 + f * 64 + g]);
        }
    }
}

// ---------------------------------------------------------------------------
// k_comb: temporal mixing; fp16 inputs; writes mix A-operand g_A2
// ---------------------------------------------------------------------------
__global__ __launch_bounds__(256)
void k_comb(const float* __restrict__ At, const float* __restrict__ sv)
{
    __shared__ float sAt[64];
    const int tid = threadIdx.x;
    if (tid < 64) sAt[tid] = At[tid];
    __syncthreads();

    const int g  = tid >> 6, f = tid & 63;
    const int bx = blockIdx.x * 4 + g;      // 0..3999
    const int b  = bx / 500;
    const int s  = bx - b * 500;

    const size_t base = (size_t)s * CN + b * (T_DIM * FO) + f;
    const size_t m2off = (size_t)512 * CN;

    float m0[8], m1v[8], m2v[8];
    #pragma unroll
    for (int t = 0; t < 8; t++) {
        m0[t]  = __half2float(g_Zh[base + t * 64]);
        m1v[t] = __half2float(g_Ch[base + t * 64]);
        m2v[t] = __half2float(g_Ch[m2off + base + t * 64]);
    }
    const float s0 = sv[0], s1 = sv[1], s2 = sv[2], s3 = sv[3];
    const float c00 = s0 * s0, c01 = 2.f * s0 * s1, c02 = s1 * s1;
    const float c10 = 2.f * s0 * s2, c11 = 2.f * (s0 * s3 + s1 * s2), c12 = 2.f * s1 * s3;
    const float c20 = s2 * s2, c21 = 2.f * s2 * s3, c22 = s3 * s3;

    float n10[8], n11[8], n12[8];
    #pragma unroll
    for (int t = 0; t < 8; t++) {
        float a0 = 0.f, a1 = 0.f, a2 = 0.f;
        #pragma unroll
        for (int u = 0; u < 8; u++) {
            const float w = sAt[t * 8 + u];
            a0 += w * m0[u]; a1 += w * m1v[u]; a2 += w * m2v[u];
        }
        n10[t] = a0; n11[t] = a1; n12[t] = a2;
    }
    #pragma unroll
    for (int t = 0; t < 8; t++) {
        float a0 = 0.f, a1 = 0.f, a2 = 0.f;
        #pragma unroll
        for (int u = 0; u < 8; u++) {
            const float w = sAt[t * 8 + u];
            a0 += w * n10[u]; a1 += w * n11[u]; a2 += w * n12[u];
        }
        const float y1 = s0 * m0[t] + s1 * m1v[t] + s2 * n10[t] + s3 * n11[t];
        const float y2 = c00 * m0[t] + c01 * m1v[t] + c02 * m2v[t]
                       + c10 * n10[t] + c11 * n11[t] + c12 * n12[t]
                       + c20 * a0 + c21 * a1 + c22 * a2;

        __half* ap = g_A2 + (size_t)((b * 8 + t) * 512 + s) * K2;
        ap[f]       = __float2half_rn(m0[t]);
        ap[64 + f]  = __float2half_rn(y1);
        ap[128 + f] = __float2half_rn(y2);
    }
}

// ---------------------------------------------------------------------------
// k_out: grid 1000, 256 thr = 4 groups; W2 cached in smem.
// ---------------------------------------------------------------------------
__global__ __launch_bounds__(256)
void k_out(const float* __restrict__ W2, const float* __restrict__ b2,
           const float* __restrict__ merge, float* __restrict__ out)
{
    __shared__ float w2s[64][65];
    __shared__ float su[4][64];
    __shared__ float sm[8];

    const int tid = threadIdx.x;
    if (tid < 8) sm[tid] = merge[tid];
    for (int idx = tid; idx < 4096; idx += 256)
        w2s[idx >> 6][idx & 63] = W2[idx];
    __syncthreads();

    const int g = tid >> 6, f = tid & 63;
    const int bx = blockIdx.x * 4 + g;      // 0..3999
    const int b  = bx / 500;
    const int s  = bx - b * 500;

    const size_t base = (size_t)s * CN + b * (T_DIM * FO) + f;
    float acc = 0.f, msum = 0.f;
    #pragma unroll
    for (int t = 0; t < 8; t++) {
        acc  += sm[t] * __half2float(g_Zh[base + t * 64]);
        msum += sm[t];
    }
    su[g][f] = acc;
    __syncthreads();

    float o = msum * b2[f];
    #pragma unroll 8
    for (int k = 0; k < 64; k++) o += w2s[f][k] * su[g][k];
    out[(size_t)bx * 64 + f] = o;
}

// ---------------------------------------------------------------------------
extern "C" void kernel_launch(void* const* d_in, const int* in_sizes, int n_in,
                              void* d_out, int out_size)
{
    const float* x     = (const float*)d_in[0];
    const float* At    = (const float*)d_in[1];
    const float* As    = (const float*)d_in[2];
    const float* sv    = (const float*)d_in[3];
    const float* H     = (const float*)d_in[4];
    const float* W1    = (const float*)d_in[5];
    const float* b1    = (const float*)d_in[6];
    const float* W2    = (const float*)d_in[7];
    const float* b2    = (const float*)d_in[8];
    const float* merge = (const float*)d_in[9];
    float* out = (float*)d_out;

    cudaFuncSetAttribute(tg_main, cudaFuncAttributeMaxDynamicSharedMemorySize, SM_MAIN);
    cudaFuncSetAttribute(tg_mix,  cudaFuncAttributeMaxDynamicSharedMemorySize, SM_MIX);

    __half *Ah, *BT, *Bh, *A2, *Ht, *Ch;
    cudaGetSymbolAddress((void**)&Ah, g_Ahalf);
    cudaGetSymbolAddress((void**)&BT, g_BT);
    cudaGetSymbolAddress((void**)&Bh, g_Bh);
    cudaGetSymbolAddress((void**)&A2, g_A2);
    cudaGetSymbolAddress((void**)&Ht, g_Ht);
    cudaGetSymbolAddress((void**)&Ch, g_Ch);

    // 0: inproj + As conversion + Ht conversion (merged)
    k_prep<<<dim3(64, 15), 256>>>(x, W1, b1, As, H);
    // 1: As2 = As @ As via split-K x4 (fp32 partials), grid (4,4,4)
    tg_main<<<dim3(4, 4, 4), 256, SM_MAIN>>>(Ah, BT, Ch, 128, KH, 1);
    // 2: reduce partials -> Ahalf rows 512+ (float4, 8/thread)
    k_red<<<128, 256>>>();

    for (int l = 0; l < 3; l++) {
        // main GEMM Ch[1024,4096] = [As;As2] @ Z^T, K=512
        tg_main<<<dim3(32, 8, 1), 256, SM_MAIN>>>(Ah, Bh, Ch, KH, CN, 0);
        k_comb<<<1000, 256>>>(At, sv);
        // mix: Zh = tanh(A2 @ Ht^T); epilogue emits next layer's Bh
        tg_mix<<<256, 256, SM_MIX>>>(A2, Ht + (size_t)l * FO * K2, l < 2 ? 1 : 0);
    }

    k_out<<<1000, 256>>>(W2, b2, merge, out);
}